// round 6
// baseline (speedup 1.0000x reference)
#include <cuda_runtime.h>
#include <cstdint>

// ---------------------------------------------------------------------------
// Compile-time LUT construction (replicates the numpy table builders exactly)
// ---------------------------------------------------------------------------
struct LUTs {
    int tbl64[64];   // packed: ptype | rot<<2 | flip<<4, keyed by 6 pairwise <= bits
    int wA[17], wB[17], wC[17];  // lex-rank prefix tables for sorted tuples
};

static constexpr LUTs make_luts() {
    LUTs L = {};
    int tm[256] = {}, rm[256] = {}, fm[256] = {};
    for (int i = 0; i < 256; i++) { tm[i] = 10; rm[i] = 10; fm[i] = 10; }
    const int pats[3][4] = { {0,1,2,3}, {0,1,3,2}, {0,2,3,1} };
    for (int pt = 0; pt < 3; ++pt) {
        int p[4] = { pats[pt][0], pats[pt][1], pats[pt][2], pats[pt][3] };
        for (int fl = 0; fl < 2; ++fl) {
            for (int ro = 0; ro < 4; ++ro) {
                int q[4] = { p[0], p[1], p[2], p[3] };
                for (int k = 0; k < ro; k++) {           // np.rot90 once
                    int t0 = q[0], t1 = q[1], t2 = q[2], t3 = q[3];
                    q[0] = t1; q[1] = t3; q[2] = t0; q[3] = t2;
                }
                int id = ((q[0]*4 + q[1])*4 + q[2])*4 + q[3];
                tm[id] = pt; rm[id] = ro; fm[id] = fl;
            }
            int t0 = p[0], t1 = p[1], t2 = p[2], t3 = p[3]; // p = p[:, ::-1]
            p[0] = t1; p[1] = t0; p[2] = t3; p[3] = t2;
        }
    }
    for (int key = 0; key < 64; ++key) {
        int p01 =  key       & 1;
        int p02 = (key >> 1) & 1;
        int p03 = (key >> 2) & 1;
        int p12 = (key >> 3) & 1;
        int p13 = (key >> 4) & 1;
        int p23 = (key >> 5) & 1;
        int r0 = (1-p01) + (1-p02) + (1-p03);
        int r1 = p01 + (1-p12) + (1-p13);
        int r2 = p02 + p12 + (1-p23);
        int r3 = p03 + p13 + p23;
        int rr[4] = { r0, r1, r2, r3 };
        int seen[4] = {0,0,0,0};
        bool ok = true;
        for (int k = 0; k < 4; k++) {
            if (rr[k] < 0 || rr[k] > 3) { ok = false; break; }
            seen[rr[k]]++;
        }
        if (ok) for (int k = 0; k < 4; k++) if (seen[k] != 1) ok = false;
        int val = 0;
        if (ok) {
            int id = ((r0*4 + r1)*4 + r2)*4 + r3;
            int ty = tm[id], ro = rm[id], fl = fm[id];
            if (ty > 2) ty = 2;
            if (ro > 3) ro = 0;
            if (fl > 1) fl = 0;
            val = ty | (ro << 2) | (fl << 4);
        }
        L.tbl64[key] = val;
    }
    int S1 = 0, S2 = 0, S3 = 0;
    for (int x = 0; x < 17; ++x) {
        L.wA[x] = S3 - S2;
        L.wB[x] = S2 - S1;
        L.wC[x] = S1 - x;
        S1 += 17 - x;
        S2 += (18 - x) * (17 - x) / 2;
        S3 += (19 - x) * (18 - x) * (17 - x) / 6;
    }
    return L;
}

__constant__ LUTs g_luts = make_luts();

// ---------------------------------------------------------------------------
// Kernel: 4 lanes per index; lane r gathers its output row DIRECTLY from the
// source tile (row or column walk with signed stride) — no shuffles at all.
//
// Source mapping (C[i][j] = B[i][fl?3-j:j]; R1[i][j]=C[j][3-i];
// R2[i][j]=C[3-i][3-j]; R3[i][j]=C[3-j][i]):
//   ro=0: out[r][j] = B[r   ][fl?3-j:j] -> row  r,   dir=fl
//   ro=2: out[r][j] = B[3-r ][fl?j:3-j] -> row  3-r, dir=!fl
//   ro=1: out[r][j] = B[j   ][fl?r:3-r] -> col  (fl?r:3-r),  ascending
//   ro=3: out[r][j] = B[3-j ][fl?3-r:r] -> col  (fl?3-r:r),  descending
// ---------------------------------------------------------------------------
__global__ __launch_bounds__(256)
void lut_symmetric_kernel(const int*   __restrict__ index,
                          const float* __restrict__ w0,
                          const float* __restrict__ w1,
                          const float* __restrict__ w2,
                          float*       __restrict__ out,
                          int n)
{
    __shared__ int s_tbl[64];
    __shared__ int sA[17], sB[17], sC[17];
    {
        int tid = threadIdx.x;
        if (tid < 64)                 s_tbl[tid]    = g_luts.tbl64[tid];
        if (tid >= 64  && tid < 81)   sA[tid - 64]  = g_luts.wA[tid - 64];
        if (tid >= 96  && tid < 113)  sB[tid - 96]  = g_luts.wB[tid - 96];
        if (tid >= 128 && tid < 145)  sC[tid - 128] = g_luts.wC[tid - 128];
    }
    __syncthreads();

    unsigned gid = blockIdx.x * blockDim.x + threadIdx.x;
    unsigned idx = gid >> 2;          // index id
    int r = gid & 3;                  // output row owned by this lane
    if (idx >= (unsigned)n) return;   // no cross-lane ops -> safe early exit

    // ---- decode base-17 digits ----
    unsigned i = (unsigned)__ldg(&index[idx]);
    unsigned d = i % 17u; i /= 17u;
    unsigned c = i % 17u; i /= 17u;
    unsigned b = i % 17u;
    unsigned a = i / 17u;

    // ---- symmetry class from pairwise comparison bits ----
    int key =  (int)(a <= b)
            | ((int)(a <= c) << 1)
            | ((int)(a <= d) << 2)
            | ((int)(b <= c) << 3)
            | ((int)(b <= d) << 4)
            | ((int)(c <= d) << 5);
    int packed = s_tbl[key];
    int ty = packed & 3;
    int ro = (packed >> 2) & 3;
    int fl = (packed >> 4) & 1;

    // ---- sort digits (network) -> lex rank -> widx ----
    unsigned l0 = min(a, b), h0 = max(a, b);
    unsigned l1 = min(c, d), h1 = max(c, d);
    unsigned s0 = min(l0, l1), m0 = max(l0, l1);
    unsigned m1 = min(h0, h1), s3 = max(h0, h1);
    unsigned s1 = min(m0, m1), s2 = max(m0, m1);
    int widx = sA[s0] + sB[s1] + sC[s2] + (int)s3;

    // ---- per-lane source walk: element offset = base + step*j ----
    int rr3  = 3 - r;
    bool odd = (ro & 1) != 0;

    // row case (ro even)
    int srow = (ro == 0) ? r : rr3;
    int dirR = fl ^ (ro >> 1);                 // ro=0: fl ; ro=2: !fl
    int baseR = srow * 4 + (dirR ? 3 : 0);
    int stepR = dirR ? -1 : 1;

    // column case (ro odd)
    int scol = ((fl ^ (int)(ro == 3)) != 0) ? r : rr3;
    int dirC = (ro == 3);
    int baseC = (dirC ? 12 : 0) + scol;
    int stepC = dirC ? -4 : 4;

    int base = odd ? baseC : baseR;
    int step = odd ? stepC : stepR;

    const float* wp = (ty == 0) ? w0 : ((ty == 1) ? w1 : w2);
    const float* p  = wp + (unsigned)widx * 16u + base;

    float v0 = __ldg(p);
    float v1 = __ldg(p + step);
    float v2 = __ldg(p + 2 * step);
    float v3 = __ldg(p + 3 * step);

    // ---- round (half-to-even == jnp.round) + clip ----
    float o0 = fminf(fmaxf(rintf(v0), -128.0f), 127.0f);
    float o1 = fminf(fmaxf(rintf(v1), -128.0f), 127.0f);
    float o2 = fminf(fmaxf(rintf(v2), -128.0f), 127.0f);
    float o3 = fminf(fmaxf(rintf(v3), -128.0f), 127.0f);

    *reinterpret_cast<float4*>(out + (size_t)idx * 16u + (unsigned)r * 4u)
        = make_float4(o0, o1, o2, o3);
}

// ---------------------------------------------------------------------------
// Harness entry
// ---------------------------------------------------------------------------
extern "C" void kernel_launch(void* const* d_in, const int* in_sizes, int n_in,
                              void* d_out, int out_size)
{
    const int*   index = (const int*)  d_in[0];
    const float* w0    = (const float*)d_in[1];
    const float* w1    = (const float*)d_in[2];
    const float* w2    = (const float*)d_in[3];
    float*       out   = (float*)      d_out;
    int n = in_sizes[0];

    unsigned total = (unsigned)n * 4u;
    unsigned block = 256;
    unsigned grid  = (total + block - 1) / block;
    lut_symmetric_kernel<<<grid, block>>>(index, w0, w1, w2, out, n);
}

// round 7
// speedup vs baseline: 2.0327x; 2.0327x over previous
#include <cuda_runtime.h>
#include <cstdint>

// ---------------------------------------------------------------------------
// Compile-time LUT construction (replicates the numpy table builders exactly)
// ---------------------------------------------------------------------------
struct LUTs {
    int tbl64[64];   // packed: ptype | rot<<2 | flip<<4, keyed by 6 pairwise <= bits
    int wA[17], wB[17], wC[17];  // lex-rank prefix tables for sorted tuples
};

static constexpr LUTs make_luts() {
    LUTs L = {};
    int tm[256] = {}, rm[256] = {}, fm[256] = {};
    for (int i = 0; i < 256; i++) { tm[i] = 10; rm[i] = 10; fm[i] = 10; }
    const int pats[3][4] = { {0,1,2,3}, {0,1,3,2}, {0,2,3,1} };
    for (int pt = 0; pt < 3; ++pt) {
        int p[4] = { pats[pt][0], pats[pt][1], pats[pt][2], pats[pt][3] };
        for (int fl = 0; fl < 2; ++fl) {
            for (int ro = 0; ro < 4; ++ro) {
                int q[4] = { p[0], p[1], p[2], p[3] };
                for (int k = 0; k < ro; k++) {           // np.rot90 once
                    int t0 = q[0], t1 = q[1], t2 = q[2], t3 = q[3];
                    q[0] = t1; q[1] = t3; q[2] = t0; q[3] = t2;
                }
                int id = ((q[0]*4 + q[1])*4 + q[2])*4 + q[3];
                tm[id] = pt; rm[id] = ro; fm[id] = fl;
            }
            int t0 = p[0], t1 = p[1], t2 = p[2], t3 = p[3]; // p = p[:, ::-1]
            p[0] = t1; p[1] = t0; p[2] = t3; p[3] = t2;
        }
    }
    for (int key = 0; key < 64; ++key) {
        int p01 =  key       & 1;
        int p02 = (key >> 1) & 1;
        int p03 = (key >> 2) & 1;
        int p12 = (key >> 3) & 1;
        int p13 = (key >> 4) & 1;
        int p23 = (key >> 5) & 1;
        int r0 = (1-p01) + (1-p02) + (1-p03);
        int r1 = p01 + (1-p12) + (1-p13);
        int r2 = p02 + p12 + (1-p23);
        int r3 = p03 + p13 + p23;
        int rr[4] = { r0, r1, r2, r3 };
        int seen[4] = {0,0,0,0};
        bool ok = true;
        for (int k = 0; k < 4; k++) {
            if (rr[k] < 0 || rr[k] > 3) { ok = false; break; }
            seen[rr[k]]++;
        }
        if (ok) for (int k = 0; k < 4; k++) if (seen[k] != 1) ok = false;
        int val = 0;
        if (ok) {
            int id = ((r0*4 + r1)*4 + r2)*4 + r3;
            int ty = tm[id], ro = rm[id], fl = fm[id];
            if (ty > 2) ty = 2;
            if (ro > 3) ro = 0;
            if (fl > 1) fl = 0;
            val = ty | (ro << 2) | (fl << 4);
        }
        L.tbl64[key] = val;
    }
    int S1 = 0, S2 = 0, S3 = 0;
    for (int x = 0; x < 17; ++x) {
        L.wA[x] = S3 - S2;
        L.wB[x] = S2 - S1;
        L.wC[x] = S1 - x;
        S1 += 17 - x;
        S2 += (18 - x) * (17 - x) / 2;
        S3 += (19 - x) * (18 - x) * (17 - x) / 6;
    }
    return L;
}

__constant__ LUTs g_luts = make_luts();

// Full materialized output for every possible packed index value: 17^4 tiles
// of 4x4 floats = 83521 * 64 B = 5.3 MiB. L2-resident on B200.
#define NVALS 83521
__device__ float4 g_table[NVALS * 4];

// ---------------------------------------------------------------------------
// Kernel 1: materialize g_table[v] for all v in [0, 17^4).
// 4 lanes per value; lane r produces output row r via a direct row/col walk
// of the source tile (verified correct in round 5/6).
//
// Source mapping (C[i][j] = B[i][fl?3-j:j]; R1[i][j]=C[j][3-i];
// R2[i][j]=C[3-i][3-j]; R3[i][j]=C[3-j][i]):
//   ro=0: row r,   dir=fl     ro=2: row 3-r, dir=!fl
//   ro=1: col (fl?r:3-r) ascending     ro=3: col (fl?3-r:r) descending
// ---------------------------------------------------------------------------
__global__ __launch_bounds__(256)
void build_table_kernel(const float* __restrict__ w0,
                        const float* __restrict__ w1,
                        const float* __restrict__ w2)
{
    __shared__ int s_tbl[64];
    __shared__ int sA[17], sB[17], sC[17];
    {
        int tid = threadIdx.x;
        if (tid < 64)                 s_tbl[tid]    = g_luts.tbl64[tid];
        if (tid >= 64  && tid < 81)   sA[tid - 64]  = g_luts.wA[tid - 64];
        if (tid >= 96  && tid < 113)  sB[tid - 96]  = g_luts.wB[tid - 96];
        if (tid >= 128 && tid < 145)  sC[tid - 128] = g_luts.wC[tid - 128];
    }
    __syncthreads();

    unsigned gid = blockIdx.x * blockDim.x + threadIdx.x;
    unsigned v = gid >> 2;            // packed index value
    int r = gid & 3;                  // output row owned by this lane
    if (v >= NVALS) return;

    // ---- decode base-17 digits ----
    unsigned i = v;
    unsigned d = i % 17u; i /= 17u;
    unsigned c = i % 17u; i /= 17u;
    unsigned b = i % 17u;
    unsigned a = i / 17u;

    // ---- symmetry class from pairwise comparison bits ----
    int key =  (int)(a <= b)
            | ((int)(a <= c) << 1)
            | ((int)(a <= d) << 2)
            | ((int)(b <= c) << 3)
            | ((int)(b <= d) << 4)
            | ((int)(c <= d) << 5);
    int packed = s_tbl[key];
    int ty = packed & 3;
    int ro = (packed >> 2) & 3;
    int fl = (packed >> 4) & 1;

    // ---- sort digits (network) -> lex rank -> widx ----
    unsigned l0 = min(a, b), h0 = max(a, b);
    unsigned l1 = min(c, d), h1 = max(c, d);
    unsigned s0 = min(l0, l1), m0 = max(l0, l1);
    unsigned m1 = min(h0, h1), s3 = max(h0, h1);
    unsigned s1 = min(m0, m1), s2 = max(m0, m1);
    int widx = sA[s0] + sB[s1] + sC[s2] + (int)s3;

    // ---- per-lane source walk: element offset = base + step*j ----
    int rr3  = 3 - r;
    bool odd = (ro & 1) != 0;

    int srow = (ro == 0) ? r : rr3;            // row case (ro even)
    int dirR = fl ^ (ro >> 1);
    int baseR = srow * 4 + (dirR ? 3 : 0);
    int stepR = dirR ? -1 : 1;

    int scol = ((fl ^ (int)(ro == 3)) != 0) ? r : rr3;   // col case (ro odd)
    int dirC = (ro == 3);
    int baseC = (dirC ? 12 : 0) + scol;
    int stepC = dirC ? -4 : 4;

    int base = odd ? baseC : baseR;
    int step = odd ? stepC : stepR;

    const float* wp = (ty == 0) ? w0 : ((ty == 1) ? w1 : w2);
    const float* p  = wp + (unsigned)widx * 16u + base;

    float v0 = __ldg(p);
    float v1 = __ldg(p + step);
    float v2 = __ldg(p + 2 * step);
    float v3 = __ldg(p + 3 * step);

    // ---- round (half-to-even == jnp.round) + clip ----
    float o0 = fminf(fmaxf(rintf(v0), -128.0f), 127.0f);
    float o1 = fminf(fmaxf(rintf(v1), -128.0f), 127.0f);
    float o2 = fminf(fmaxf(rintf(v2), -128.0f), 127.0f);
    float o3 = fminf(fmaxf(rintf(v3), -128.0f), 127.0f);

    g_table[v * 4u + (unsigned)r] = make_float4(o0, o1, o2, o3);
}

// ---------------------------------------------------------------------------
// Kernel 2: hot pass — pure 64B gather by index.
// 4 lanes per index: lane r moves one float4. Index load broadcasts across
// the 4-lane group (same L1 line, single wavefront). Streaming store for out.
// ---------------------------------------------------------------------------
__global__ __launch_bounds__(256)
void gather_kernel(const int* __restrict__ index,
                   float4*    __restrict__ out,
                   int n)
{
    unsigned gid = blockIdx.x * blockDim.x + threadIdx.x;
    unsigned idx = gid >> 2;
    int r = gid & 3;
    if (idx >= (unsigned)n) return;

    unsigned v = (unsigned)__ldg(&index[idx]);
    float4 t = __ldg(&g_table[v * 4u + (unsigned)r]);
    __stcs(&out[(size_t)idx * 4u + (unsigned)r], t);
}

// ---------------------------------------------------------------------------
// Harness entry
// ---------------------------------------------------------------------------
extern "C" void kernel_launch(void* const* d_in, const int* in_sizes, int n_in,
                              void* d_out, int out_size)
{
    const int*   index = (const int*)  d_in[0];
    const float* w0    = (const float*)d_in[1];
    const float* w1    = (const float*)d_in[2];
    const float* w2    = (const float*)d_in[3];
    float4*      out   = (float4*)     d_out;
    int n = in_sizes[0];

    // Pass 1: materialize all 17^4 output tiles (5.3 MiB, L2-resident).
    {
        unsigned total = NVALS * 4u;
        unsigned block = 256;
        unsigned grid  = (total + block - 1) / block;
        build_table_kernel<<<grid, block>>>(w0, w1, w2);
    }
    // Pass 2: pure gather.
    {
        unsigned total = (unsigned)n * 4u;
        unsigned block = 256;
        unsigned grid  = (total + block - 1) / block;
        gather_kernel<<<grid, block>>>(index, out, n);
    }
}

// round 8
// speedup vs baseline: 2.1187x; 1.0423x over previous
#include <cuda_runtime.h>
#include <cstdint>

// ---------------------------------------------------------------------------
// Compile-time LUT construction (replicates the numpy table builders exactly)
// ---------------------------------------------------------------------------
struct LUTs {
    int tbl64[64];   // packed: ptype | rot<<2 | flip<<4, keyed by 6 pairwise <= bits
    int wA[17], wB[17], wC[17];  // lex-rank prefix tables for sorted tuples
};

static constexpr LUTs make_luts() {
    LUTs L = {};
    int tm[256] = {}, rm[256] = {}, fm[256] = {};
    for (int i = 0; i < 256; i++) { tm[i] = 10; rm[i] = 10; fm[i] = 10; }
    const int pats[3][4] = { {0,1,2,3}, {0,1,3,2}, {0,2,3,1} };
    for (int pt = 0; pt < 3; ++pt) {
        int p[4] = { pats[pt][0], pats[pt][1], pats[pt][2], pats[pt][3] };
        for (int fl = 0; fl < 2; ++fl) {
            for (int ro = 0; ro < 4; ++ro) {
                int q[4] = { p[0], p[1], p[2], p[3] };
                for (int k = 0; k < ro; k++) {           // np.rot90 once
                    int t0 = q[0], t1 = q[1], t2 = q[2], t3 = q[3];
                    q[0] = t1; q[1] = t3; q[2] = t0; q[3] = t2;
                }
                int id = ((q[0]*4 + q[1])*4 + q[2])*4 + q[3];
                tm[id] = pt; rm[id] = ro; fm[id] = fl;
            }
            int t0 = p[0], t1 = p[1], t2 = p[2], t3 = p[3]; // p = p[:, ::-1]
            p[0] = t1; p[1] = t0; p[2] = t3; p[3] = t2;
        }
    }
    for (int key = 0; key < 64; ++key) {
        int p01 =  key       & 1;
        int p02 = (key >> 1) & 1;
        int p03 = (key >> 2) & 1;
        int p12 = (key >> 3) & 1;
        int p13 = (key >> 4) & 1;
        int p23 = (key >> 5) & 1;
        int r0 = (1-p01) + (1-p02) + (1-p03);
        int r1 = p01 + (1-p12) + (1-p13);
        int r2 = p02 + p12 + (1-p23);
        int r3 = p03 + p13 + p23;
        int rr[4] = { r0, r1, r2, r3 };
        int seen[4] = {0,0,0,0};
        bool ok = true;
        for (int k = 0; k < 4; k++) {
            if (rr[k] < 0 || rr[k] > 3) { ok = false; break; }
            seen[rr[k]]++;
        }
        if (ok) for (int k = 0; k < 4; k++) if (seen[k] != 1) ok = false;
        int val = 0;
        if (ok) {
            int id = ((r0*4 + r1)*4 + r2)*4 + r3;
            int ty = tm[id], ro = rm[id], fl = fm[id];
            if (ty > 2) ty = 2;
            if (ro > 3) ro = 0;
            if (fl > 1) fl = 0;
            val = ty | (ro << 2) | (fl << 4);
        }
        L.tbl64[key] = val;
    }
    int S1 = 0, S2 = 0, S3 = 0;
    for (int x = 0; x < 17; ++x) {
        L.wA[x] = S3 - S2;
        L.wB[x] = S2 - S1;
        L.wC[x] = S1 - x;
        S1 += 17 - x;
        S2 += (18 - x) * (17 - x) / 2;
        S3 += (19 - x) * (18 - x) * (17 - x) / 6;
    }
    return L;
}

__constant__ LUTs g_luts = make_luts();

// Materialized output, quantized to int8 (values are exact integers in
// [-128,127] after round+clip). 17^4 tiles * 16 B = 1.3 MiB -> L2-resident.
// Layout: g_tab8[v*4 + r] packs row r of tile v as 4 s8 bytes (j=0 in LSB).
#define NVALS 83521
__device__ unsigned g_tab8[NVALS * 4];

// ---------------------------------------------------------------------------
// Kernel 1: materialize the int8 table.
// 4 lanes per value; lane r produces output row r via a direct row/col walk
// of the source tile (mapping verified in rounds 5-7).
//   ro=0: row r,   dir=fl     ro=2: row 3-r, dir=!fl
//   ro=1: col (fl?r:3-r) ascending     ro=3: col (fl?3-r:r) descending
// ---------------------------------------------------------------------------
__global__ __launch_bounds__(256)
void build_table_kernel(const float* __restrict__ w0,
                        const float* __restrict__ w1,
                        const float* __restrict__ w2)
{
    __shared__ int s_tbl[64];
    __shared__ int sA[17], sB[17], sC[17];
    {
        int tid = threadIdx.x;
        if (tid < 64)                 s_tbl[tid]    = g_luts.tbl64[tid];
        if (tid >= 64  && tid < 81)   sA[tid - 64]  = g_luts.wA[tid - 64];
        if (tid >= 96  && tid < 113)  sB[tid - 96]  = g_luts.wB[tid - 96];
        if (tid >= 128 && tid < 145)  sC[tid - 128] = g_luts.wC[tid - 128];
    }
    __syncthreads();

    unsigned gid = blockIdx.x * blockDim.x + threadIdx.x;
    unsigned v = gid >> 2;            // packed index value
    int r = gid & 3;                  // output row owned by this lane
    if (v >= NVALS) return;

    // ---- decode base-17 digits ----
    unsigned i = v;
    unsigned d = i % 17u; i /= 17u;
    unsigned c = i % 17u; i /= 17u;
    unsigned b = i % 17u;
    unsigned a = i / 17u;

    // ---- symmetry class from pairwise comparison bits ----
    int key =  (int)(a <= b)
            | ((int)(a <= c) << 1)
            | ((int)(a <= d) << 2)
            | ((int)(b <= c) << 3)
            | ((int)(b <= d) << 4)
            | ((int)(c <= d) << 5);
    int packed = s_tbl[key];
    int ty = packed & 3;
    int ro = (packed >> 2) & 3;
    int fl = (packed >> 4) & 1;

    // ---- sort digits (network) -> lex rank -> widx ----
    unsigned l0 = min(a, b), h0 = max(a, b);
    unsigned l1 = min(c, d), h1 = max(c, d);
    unsigned s0 = min(l0, l1), m0 = max(l0, l1);
    unsigned m1 = min(h0, h1), s3 = max(h0, h1);
    unsigned s1 = min(m0, m1), s2 = max(m0, m1);
    int widx = sA[s0] + sB[s1] + sC[s2] + (int)s3;

    // ---- per-lane source walk: element offset = base + step*j ----
    int rr3  = 3 - r;
    bool odd = (ro & 1) != 0;

    int srow = (ro == 0) ? r : rr3;            // row case (ro even)
    int dirR = fl ^ (ro >> 1);
    int baseR = srow * 4 + (dirR ? 3 : 0);
    int stepR = dirR ? -1 : 1;

    int scol = ((fl ^ (int)(ro == 3)) != 0) ? r : rr3;   // col case (ro odd)
    int dirC = (ro == 3);
    int baseC = (dirC ? 12 : 0) + scol;
    int stepC = dirC ? -4 : 4;

    int base = odd ? baseC : baseR;
    int step = odd ? stepC : stepR;

    const float* wp = (ty == 0) ? w0 : ((ty == 1) ? w1 : w2);
    const float* p  = wp + (unsigned)widx * 16u + base;

    float v0 = __ldg(p);
    float v1 = __ldg(p + step);
    float v2 = __ldg(p + 2 * step);
    float v3 = __ldg(p + 3 * step);

    // ---- round (half-to-even == jnp.round) + clip, quantize to s8 ----
    int q0 = (int)fminf(fmaxf(rintf(v0), -128.0f), 127.0f);
    int q1 = (int)fminf(fmaxf(rintf(v1), -128.0f), 127.0f);
    int q2 = (int)fminf(fmaxf(rintf(v2), -128.0f), 127.0f);
    int q3 = (int)fminf(fmaxf(rintf(v3), -128.0f), 127.0f);

    unsigned w =  ((unsigned)q0 & 0xffu)
               | (((unsigned)q1 & 0xffu) << 8)
               | (((unsigned)q2 & 0xffu) << 16)
               | (((unsigned)q3 & 0xffu) << 24);

    g_tab8[v * 4u + (unsigned)r] = w;
}

// ---------------------------------------------------------------------------
// Kernel 2: hot pass — gather 4 bytes per lane, convert s8->f32, write 16 B.
// 4 lanes per index (group covers one 16B table entry + one 64B output tile).
// Stores use streaming hint (no reuse).
// ---------------------------------------------------------------------------
__global__ __launch_bounds__(256)
void gather_kernel(const int* __restrict__ index,
                   float4*    __restrict__ out,
                   int n)
{
    unsigned gid = blockIdx.x * blockDim.x + threadIdx.x;
    unsigned idx = gid >> 2;
    int r = gid & 3;
    if (idx >= (unsigned)n) return;

    unsigned v = (unsigned)__ldg(&index[idx]);
    unsigned w = __ldg(&g_tab8[v * 4u + (unsigned)r]);

    // s8 -> f32 (exact; values already rounded+clipped at build time)
    float o0 = (float)(int)((signed char)( w        & 0xffu));
    float o1 = (float)(int)((signed char)((w >> 8)  & 0xffu));
    float o2 = (float)(int)((signed char)((w >> 16) & 0xffu));
    float o3 = (float)(int)((signed char)( w >> 24));

    __stcs(&out[(size_t)idx * 4u + (unsigned)r], make_float4(o0, o1, o2, o3));
}

// ---------------------------------------------------------------------------
// Harness entry
// ---------------------------------------------------------------------------
extern "C" void kernel_launch(void* const* d_in, const int* in_sizes, int n_in,
                              void* d_out, int out_size)
{
    const int*   index = (const int*)  d_in[0];
    const float* w0    = (const float*)d_in[1];
    const float* w1    = (const float*)d_in[2];
    const float* w2    = (const float*)d_in[3];
    float4*      out   = (float4*)     d_out;
    int n = in_sizes[0];

    // Pass 1: materialize all 17^4 tiles as int8 (1.3 MiB, L2-resident).
    {
        unsigned total = NVALS * 4u;
        unsigned block = 256;
        unsigned grid  = (total + block - 1) / block;
        build_table_kernel<<<grid, block>>>(w0, w1, w2);
    }
    // Pass 2: gather + s8->f32 expand.
    {
        unsigned total = (unsigned)n * 4u;
        unsigned block = 256;
        unsigned grid  = (total + block - 1) / block;
        gather_kernel<<<grid, block>>>(index, out, n);
    }
}